// round 8
// baseline (speedup 1.0000x reference)
#include <cuda_runtime.h>
#include <math.h>

#define NB 4096
#define NC 512
#define NHW 196
#define NE 64
#define TOPK 8

#define BG 8              // batches per block
#define CG 64             // channels per block (kernel A)
#define NCG (NC / CG)     // 8 channel groups

// Partial logits [cg][b][128] (16 MB). Per-batch slot layout:
// slot = (e&31)*4 + m*2 + (e>>5), m=0 route / m=1 noise  ->
// float4 at [lane*4] = {R[lane], R[lane+32], N[lane], N[lane+32]}.
// Every slot is written every call: no reset needed, bit-deterministic.
__device__ __align__(16) float g_part[NCG * NB * 128];

// packed fp32x2 FMA (SASS FFMA2 — only reachable via PTX)
#define FMA2(acc, a, b) \
    asm("fma.rn.f32x2 %0, %1, %2, %0;" : "+l"(acc) : "l"(a), "l"(b))

__device__ __forceinline__ float pair_sum(unsigned long long v) {
    return __uint_as_float((unsigned)v) + __uint_as_float((unsigned)(v >> 32));
}

// ---------------------------------------------------------------------------
// Kernel A: fused pool + partial routing GEMM.
// Block = 8 batches x 64 channels. Phase 1: warp w pools batch b0+w's 64
// channels (4 rows in flight, 8 front-batched LDG.128). Phase 2: thread =
// (output o in [0,128), half ph in [0,2)) computes 8 partial dots over the
// 64-channel slice with f32x2, writes g_part. No atomics.
// ---------------------------------------------------------------------------
__global__ void __launch_bounds__(256, 3) fused_pool_gemm(
    const float* __restrict__ x,
    const float* __restrict__ Wr,
    const float* __restrict__ Wn)
{
    __shared__ __align__(16) float sp[BG * CG];   // 2 KB pooled slice

    const int tid  = threadIdx.x;
    const int wid  = tid >> 5;
    const int lane = tid & 31;

    const int bg = blockIdx.x / NCG;
    const int cg = blockIdx.x % NCG;
    const int b0 = bg * BG;
    const int c0 = cg * CG;

    // ---------------- Phase 1: pool (warp = one batch, 64 channels) ----------
    {
        const float* bbase = x + ((size_t)(b0 + wid) * NC + c0) * NHW;
        const bool p = (lane < 17);
#pragma unroll 1
        for (int it = 0; it < CG / 4; it++) {
            const int c = it * 4;
            const float4* r0 = reinterpret_cast<const float4*>(bbase + (size_t)(c + 0) * NHW);
            const float4* r1 = reinterpret_cast<const float4*>(bbase + (size_t)(c + 1) * NHW);
            const float4* r2 = reinterpret_cast<const float4*>(bbase + (size_t)(c + 2) * NHW);
            const float4* r3 = reinterpret_cast<const float4*>(bbase + (size_t)(c + 3) * NHW);
            float4 a0 = r0[lane], a1 = r1[lane], a2 = r2[lane], a3 = r3[lane];
            float4 b0v, b1v, b2v, b3v;
            if (p) { b0v = r0[32 + lane]; b1v = r1[32 + lane];
                     b2v = r2[32 + lane]; b3v = r3[32 + lane]; }
            float s0 = (a0.x + a0.y) + (a0.z + a0.w);
            float s1 = (a1.x + a1.y) + (a1.z + a1.w);
            float s2 = (a2.x + a2.y) + (a2.z + a2.w);
            float s3 = (a3.x + a3.y) + (a3.z + a3.w);
            if (p) {
                s0 += (b0v.x + b0v.y) + (b0v.z + b0v.w);
                s1 += (b1v.x + b1v.y) + (b1v.z + b1v.w);
                s2 += (b2v.x + b2v.y) + (b2v.z + b2v.w);
                s3 += (b3v.x + b3v.y) + (b3v.z + b3v.w);
            }
#pragma unroll
            for (int o = 16; o; o >>= 1) {
                s0 += __shfl_xor_sync(0xffffffffu, s0, o);
                s1 += __shfl_xor_sync(0xffffffffu, s1, o);
                s2 += __shfl_xor_sync(0xffffffffu, s2, o);
                s3 += __shfl_xor_sync(0xffffffffu, s3, o);
            }
            if (lane == 0) {
                sp[wid * CG + c + 0] = s0 * (1.0f / 196.0f);
                sp[wid * CG + c + 1] = s1 * (1.0f / 196.0f);
                sp[wid * CG + c + 2] = s2 * (1.0f / 196.0f);
                sp[wid * CG + c + 3] = s3 * (1.0f / 196.0f);
            }
        }
    }
    __syncthreads();

    // ---------------- Phase 2: partial GEMM over this 64-channel slice -------
    const int o  = tid >> 1;        // output 0..127 (64 route + 64 noise)
    const int ph = tid & 1;         // channel-half 0..1 (32 channels each)
    const int m  = o >> 6;
    const int e  = o & 63;

    const ulonglong2* Wp = reinterpret_cast<const ulonglong2*>(m ? Wn : Wr)
                           + (size_t)e * (NC / 4) + (c0 >> 2) + ph * 8;
    ulonglong2 wv[8];
#pragma unroll
    for (int j = 0; j < 8; j++) wv[j] = __ldg(&Wp[j]);

    const ulonglong2* sp2 = reinterpret_cast<const ulonglong2*>(sp);
    float res[BG];
#pragma unroll
    for (int r = 0; r < BG; r++) {
        unsigned long long a = 0ull;
        const ulonglong2* pr = sp2 + r * (CG / 4) + ph * 8;
#pragma unroll
        for (int j = 0; j < 8; j++) {
            ulonglong2 pv = pr[j];
            FMA2(a, pv.x, wv[j].x);
            FMA2(a, pv.y, wv[j].y);
        }
        float v = pair_sum(a);
        v += __shfl_xor_sync(0xffffffffu, v, 1);   // combine the two halves
        res[r] = v;
    }
    if (ph == 0) {
        const int slot = (e & 31) * 4 + m * 2 + (e >> 5);
        float* gp = g_part + (size_t)cg * NB * 128 + (size_t)b0 * 128 + slot;
#pragma unroll
        for (int r = 0; r < BG; r++) gp[r * 128] = res[r];
    }
}

// ---------------------------------------------------------------------------
// Kernel B: reduce partials + biases + softmax + noise + top-8 + renorm.
// Block = 8 warps = 8 batches; lane owns experts (lane, lane+32) via one
// float4 per channel-group.
// ---------------------------------------------------------------------------
__global__ __launch_bounds__(256) void finalize_kernel(
    const float* __restrict__ noise,
    const float* __restrict__ br, const float* __restrict__ bn,
    float* __restrict__ out)
{
    const int tid  = threadIdx.x;
    const int wid  = tid >> 5;
    const int lane = tid & 31;
    const int b    = blockIdx.x * BG + wid;

    const float4* gp = reinterpret_cast<const float4*>(g_part) + (size_t)b * 32 + lane;
    float4 s4 = make_float4(0.f, 0.f, 0.f, 0.f);
#pragma unroll
    for (int cg = 0; cg < NCG; cg++) {
        float4 v = gp[(size_t)cg * NB * 32];
        s4.x += v.x; s4.y += v.y; s4.z += v.z; s4.w += v.w;
    }
    float lg0 = s4.x + br[lane];
    float lg1 = s4.y + br[lane + 32];
    float nl0 = s4.z + bn[lane];
    float nl1 = s4.w + bn[lane + 32];

    float* out_rtr = out;
    float* out_idx = out + (size_t)NB * TOPK;
    float* out_nzy = out + (size_t)2 * NB * TOPK;

    // softmax(route logits) over 64
    float m = fmaxf(lg0, lg1);
#pragma unroll
    for (int o = 16; o; o >>= 1) m = fmaxf(m, __shfl_xor_sync(0xffffffffu, m, o));
    float e0v = __expf(lg0 - m), e1v = __expf(lg1 - m);
    float s = e0v + e1v;
#pragma unroll
    for (int o = 16; o; o >>= 1) s += __shfl_xor_sync(0xffffffffu, s, o);
    float inv = __frcp_rn(s);
    float smL0 = e0v * inv, smL1 = e1v * inv;

    // noise branch: z = noise * softplus(noise_logits); softmax(z)
    float sp0 = fmaxf(nl0, 0.0f) + log1pf(__expf(-fabsf(nl0)));
    float sp1 = fmaxf(nl1, 0.0f) + log1pf(__expf(-fabsf(nl1)));
    float z0 = noise[(size_t)b * NE + lane]      * sp0;
    float z1 = noise[(size_t)b * NE + lane + 32] * sp1;
    float mn = fmaxf(z0, z1);
#pragma unroll
    for (int o = 16; o; o >>= 1) mn = fmaxf(mn, __shfl_xor_sync(0xffffffffu, mn, o));
    float f0 = __expf(z0 - mn), f1 = __expf(z1 - mn);
    float sn = f0 + f1;
#pragma unroll
    for (int o = 16; o; o >>= 1) sn += __shfl_xor_sync(0xffffffffu, sn, o);
    float invn = __frcp_rn(sn);

    float noisy0 = smL0 + f0 * invn;
    float noisy1 = smL1 + f1 * invn;

    out_nzy[(size_t)b * NE + lane]      = noisy0;
    out_nzy[(size_t)b * NE + lane + 32] = noisy1;

    // top-8: iterative warp argmax; tie-break = lowest index (lax.top_k)
    float v0 = noisy0, v1 = noisy1;
    float topv[TOPK];
    int   topi[TOPK];
#pragma unroll
    for (int k = 0; k < TOPK; k++) {
        float bv; int bi;
        if (v0 >= v1) { bv = v0; bi = lane; }
        else          { bv = v1; bi = lane + 32; }
#pragma unroll
        for (int o = 16; o; o >>= 1) {
            float ov = __shfl_xor_sync(0xffffffffu, bv, o);
            int   oi = __shfl_xor_sync(0xffffffffu, bi, o);
            if (ov > bv || (ov == bv && oi < bi)) { bv = ov; bi = oi; }
        }
        topv[k] = bv; topi[k] = bi;
        if      (bi == lane)      v0 = -INFINITY;
        else if (bi == lane + 32) v1 = -INFINITY;
    }

    float ssum = 0.0f, ev[TOPK];
#pragma unroll
    for (int k = 0; k < TOPK; k++) { ev[k] = __expf(topv[k] - topv[0]); ssum += ev[k]; }
    float invt = __frcp_rn(ssum);

#pragma unroll
    for (int k = 0; k < TOPK; k++) {
        if (lane == k) {
            out_rtr[(size_t)b * TOPK + k] = ev[k] * invt;
            out_idx[(size_t)b * TOPK + k] = (float)topi[k];
        }
    }
}

// ---------------------------------------------------------------------------
extern "C" void kernel_launch(void* const* d_in, const int* in_sizes, int n_in,
                              void* d_out, int out_size) {
    const float* mh      = (const float*)d_in[0];
    const float* noise   = (const float*)d_in[1];
    const float* W_route = (const float*)d_in[2];
    const float* b_route = (const float*)d_in[3];
    const float* W_noise = (const float*)d_in[4];
    const float* b_noise = (const float*)d_in[5];
    float* out = (float*)d_out;

    fused_pool_gemm<<<(NB / BG) * NCG, 256>>>(mh, W_route, W_noise);   // 4096 blocks
    finalize_kernel<<<NB / BG, 256>>>(noise, b_route, b_noise, out);   // 512 blocks
}

// round 9
// speedup vs baseline: 1.0501x; 1.0501x over previous
#include <cuda_runtime.h>
#include <math.h>

#define NB 4096
#define NC 512
#define NHW 196
#define NE 64
#define TOPK 8
#define ROWS 8

#define SPLIT_B 3584                     // batches in part 1 (7/8)

// scratch: pooled [B, C] (8 MB) — __device__ global, no allocation
__device__ __align__(16) float g_pooled[NB * NC];

// packed fp32x2 FMA (SASS FFMA2 — only reachable via PTX)
#define FMA2(acc, a, b) \
    asm("fma.rn.f32x2 %0, %1, %2, %0;" : "+l"(acc) : "l"(a), "l"(b))

__device__ __forceinline__ float pair_sum(unsigned long long v) {
    return __uint_as_float((unsigned)v) + __uint_as_float((unsigned)(v >> 32));
}

// ---------------------------------------------------------------------------
// Kernel 1: global average pool (round-1 proven shape, ~6.8 TB/s).
// One warp per (b,c) row; row0 = offset in (b,c)-row space.
// ---------------------------------------------------------------------------
__global__ __launch_bounds__(256) void pool_kernel(const float* __restrict__ x,
                                                   int row0) {
    int row = row0 + ((blockIdx.x * 256 + threadIdx.x) >> 5);
    int lane = threadIdx.x & 31;

    const float4* row4 = reinterpret_cast<const float4*>(x + (size_t)row * NHW);
    float4 a = row4[lane];
    float s = (a.x + a.y) + (a.z + a.w);
    if (lane < 17) {
        float4 b4 = row4[32 + lane];
        s += (b4.x + b4.y) + (b4.z + b4.w);
    }
#pragma unroll
    for (int o = 16; o; o >>= 1) s += __shfl_xor_sync(0xffffffffu, s, o);
    if (lane == 0) g_pooled[row] = s * (1.0f / 196.0f);
}

// ---------------------------------------------------------------------------
// Kernel 2: routing (round-6 proven kernel + batch offset).
// Block = 8 batch rows, 256 threads. thread = (expert-pair, k-phase),
// f32x2 accumulation, conflict-free LDS.128.
// ---------------------------------------------------------------------------
__global__ __launch_bounds__(256) void router_kernel(
    const float* __restrict__ noise,
    const float* __restrict__ Wr, const float* __restrict__ br,
    const float* __restrict__ Wn, const float* __restrict__ bn,
    float* __restrict__ out, int batch0)
{
    __shared__ __align__(16) float sp[ROWS * NC];   // 16 KB pooled tile
    __shared__ __align__(16) float sLog[ROWS][NE];
    __shared__ __align__(16) float sNse[ROWS][NE];

    const int tid  = threadIdx.x;
    const int wid  = tid >> 5;
    const int lane = tid & 31;
    const int b0   = batch0 + blockIdx.x * ROWS;

    {
        const float4* g4 = reinterpret_cast<const float4*>(g_pooled + (size_t)b0 * NC);
        float4* s4 = reinterpret_cast<float4*>(sp);
#pragma unroll
        for (int i = 0; i < ROWS * NC / 4 / 256; i++)
            s4[tid + i * 256] = g4[tid + i * 256];
    }
    __syncthreads();

    const int ph = tid & 7;        // k-phase 0..7
    const int e2 = tid >> 3;       // expert pair 0..31
    const int e0 = e2 * 2, e1 = e0 + 1;

    unsigned long long acc[ROWS][4];
#pragma unroll
    for (int r = 0; r < ROWS; r++)
#pragma unroll
        for (int m = 0; m < 4; m++) acc[r][m] = 0ull;

    const ulonglong2* Wr2 = reinterpret_cast<const ulonglong2*>(Wr);
    const ulonglong2* Wn2 = reinterpret_cast<const ulonglong2*>(Wn);
    const ulonglong2* sp2 = reinterpret_cast<const ulonglong2*>(sp);

#pragma unroll 2
    for (int j = 0; j < NC / 32; j++) {
        const int idx = j * 8 + ph;
        ulonglong2 wr0 = __ldg(&Wr2[e0 * (NC / 4) + idx]);
        ulonglong2 wr1 = __ldg(&Wr2[e1 * (NC / 4) + idx]);
        ulonglong2 wn0 = __ldg(&Wn2[e0 * (NC / 4) + idx]);
        ulonglong2 wn1 = __ldg(&Wn2[e1 * (NC / 4) + idx]);
#pragma unroll
        for (int r = 0; r < ROWS; r++) {
            ulonglong2 p = sp2[r * (NC / 4) + idx];
            FMA2(acc[r][0], p.x, wr0.x); FMA2(acc[r][0], p.y, wr0.y);
            FMA2(acc[r][1], p.x, wr1.x); FMA2(acc[r][1], p.y, wr1.y);
            FMA2(acc[r][2], p.x, wn0.x); FMA2(acc[r][2], p.y, wn0.y);
            FMA2(acc[r][3], p.x, wn1.x); FMA2(acc[r][3], p.y, wn1.y);
        }
    }

    const float br0 = br[e0], br1 = br[e1], bn0 = bn[e0], bn1 = bn[e1];
#pragma unroll
    for (int r = 0; r < ROWS; r++) {
        float vR0 = pair_sum(acc[r][0]);
        float vR1 = pair_sum(acc[r][1]);
        float vN0 = pair_sum(acc[r][2]);
        float vN1 = pair_sum(acc[r][3]);
#pragma unroll
        for (int o = 1; o < 8; o <<= 1) {
            vR0 += __shfl_xor_sync(0xffffffffu, vR0, o);
            vR1 += __shfl_xor_sync(0xffffffffu, vR1, o);
            vN0 += __shfl_xor_sync(0xffffffffu, vN0, o);
            vN1 += __shfl_xor_sync(0xffffffffu, vN1, o);
        }
        if (ph == 0) {
            sLog[r][e0] = vR0 + br0;
            sLog[r][e1] = vR1 + br1;
            sNse[r][e0] = vN0 + bn0;
            sNse[r][e1] = vN1 + bn1;
        }
    }
    __syncthreads();

    // -------- Postprocess: one warp per row; lane owns experts lane, lane+32 --
    float* out_rtr = out;
    float* out_idx = out + (size_t)NB * TOPK;
    float* out_nzy = out + (size_t)2 * NB * TOPK;

    const int r = wid;
    const int b = b0 + r;

    float lg0 = sLog[r][lane], lg1 = sLog[r][lane + 32];
    float nl0 = sNse[r][lane], nl1 = sNse[r][lane + 32];

    float m = fmaxf(lg0, lg1);
#pragma unroll
    for (int o = 16; o; o >>= 1) m = fmaxf(m, __shfl_xor_sync(0xffffffffu, m, o));
    float e0v = __expf(lg0 - m), e1v = __expf(lg1 - m);
    float s = e0v + e1v;
#pragma unroll
    for (int o = 16; o; o >>= 1) s += __shfl_xor_sync(0xffffffffu, s, o);
    float inv = __frcp_rn(s);
    float smL0 = e0v * inv, smL1 = e1v * inv;

    float sp0 = fmaxf(nl0, 0.0f) + log1pf(__expf(-fabsf(nl0)));
    float sp1 = fmaxf(nl1, 0.0f) + log1pf(__expf(-fabsf(nl1)));
    float z0 = noise[(size_t)b * NE + lane]      * sp0;
    float z1 = noise[(size_t)b * NE + lane + 32] * sp1;
    float mn = fmaxf(z0, z1);
#pragma unroll
    for (int o = 16; o; o >>= 1) mn = fmaxf(mn, __shfl_xor_sync(0xffffffffu, mn, o));
    float f0 = __expf(z0 - mn), f1 = __expf(z1 - mn);
    float sn = f0 + f1;
#pragma unroll
    for (int o = 16; o; o >>= 1) sn += __shfl_xor_sync(0xffffffffu, sn, o);
    float invn = __frcp_rn(sn);

    float noisy0 = smL0 + f0 * invn;
    float noisy1 = smL1 + f1 * invn;

    out_nzy[(size_t)b * NE + lane]      = noisy0;
    out_nzy[(size_t)b * NE + lane + 32] = noisy1;

    float v0 = noisy0, v1 = noisy1;
    float topv[TOPK];
    int   topi[TOPK];
#pragma unroll
    for (int k = 0; k < TOPK; k++) {
        float bv; int bi;
        if (v0 >= v1) { bv = v0; bi = lane; }
        else          { bv = v1; bi = lane + 32; }
#pragma unroll
        for (int o = 16; o; o >>= 1) {
            float ov = __shfl_xor_sync(0xffffffffu, bv, o);
            int   oi = __shfl_xor_sync(0xffffffffu, bi, o);
            if (ov > bv || (ov == bv && oi < bi)) { bv = ov; bi = oi; }
        }
        topv[k] = bv; topi[k] = bi;
        if      (bi == lane)      v0 = -INFINITY;
        else if (bi == lane + 32) v1 = -INFINITY;
    }

    float ssum = 0.0f, ev[TOPK];
#pragma unroll
    for (int k = 0; k < TOPK; k++) { ev[k] = __expf(topv[k] - topv[0]); ssum += ev[k]; }
    float invt = __frcp_rn(ssum);

#pragma unroll
    for (int k = 0; k < TOPK; k++) {
        if (lane == k) {
            out_rtr[(size_t)b * TOPK + k] = ev[k] * invt;
            out_idx[(size_t)b * TOPK + k] = (float)topi[k];
        }
    }
}

// ---------------------------------------------------------------------------
// Side stream + events (host resources, created once before first capture).
// ---------------------------------------------------------------------------
static cudaStream_t g_s2;
static cudaEvent_t  g_ev1, g_ev2, g_evJoin;
namespace {
struct StreamInit {
    StreamInit() {
        cudaStreamCreateWithFlags(&g_s2, cudaStreamNonBlocking);
        cudaEventCreateWithFlags(&g_ev1,    cudaEventDisableTiming);
        cudaEventCreateWithFlags(&g_ev2,    cudaEventDisableTiming);
        cudaEventCreateWithFlags(&g_evJoin, cudaEventDisableTiming);
    }
};
static StreamInit g_streamInit;
}

// ---------------------------------------------------------------------------
// 7/8 + 1/8 split: router for the first 7/8 hides under the last 1/8 of the
// pool stream; only a 64-block router tail is exposed.
// ---------------------------------------------------------------------------
extern "C" void kernel_launch(void* const* d_in, const int* in_sizes, int n_in,
                              void* d_out, int out_size) {
    const float* mh      = (const float*)d_in[0];
    const float* noise   = (const float*)d_in[1];
    const float* W_route = (const float*)d_in[2];
    const float* b_route = (const float*)d_in[3];
    const float* W_noise = (const float*)d_in[4];
    const float* b_noise = (const float*)d_in[5];
    float* out = (float*)d_out;

    const int rows1 = SPLIT_B * NC;                 // part-1 (b,c) rows
    const int rows2 = (NB - SPLIT_B) * NC;          // part-2 (b,c) rows

    // pool part 1 (batches [0, 3584))
    pool_kernel<<<rows1 / 8, 256>>>(mh, 0);
    cudaEventRecord(g_ev1, 0);

    // pool part 2 (batches [3584, 4096)) — runs while router part 1 executes
    pool_kernel<<<rows2 / 8, 256>>>(mh, rows1);
    cudaEventRecord(g_ev2, 0);

    // router part 1 on side stream, after pool part 1
    cudaStreamWaitEvent(g_s2, g_ev1, 0);
    router_kernel<<<SPLIT_B / ROWS, 256, 0, g_s2>>>(
        noise, W_route, b_route, W_noise, b_noise, out, 0);

    // router part 2 on side stream, after pool part 2 (and router part 1)
    cudaStreamWaitEvent(g_s2, g_ev2, 0);
    router_kernel<<<(NB - SPLIT_B) / ROWS, 256, 0, g_s2>>>(
        noise, W_route, b_route, W_noise, b_noise, out, SPLIT_B);

    // join back to the capture stream
    cudaEventRecord(g_evJoin, g_s2);
    cudaStreamWaitEvent(0, g_evJoin, 0);
}

// round 10
// speedup vs baseline: 1.0502x; 1.0001x over previous
#include <cuda_runtime.h>
#include <math.h>

#define NB 4096
#define NC 512
#define NHW 196
#define NE 64
#define TOPK 8
#define ROWS 8

// scratch: pooled [B, C] (8 MB) — __device__ global, no allocation
__device__ __align__(16) float g_pooled[NB * NC];

// packed fp32x2 FMA (SASS FFMA2 — only reachable via PTX)
#define FMA2(acc, a, b) \
    asm("fma.rn.f32x2 %0, %1, %2, %0;" : "+l"(acc) : "l"(a), "l"(b))

__device__ __forceinline__ float pair_sum(unsigned long long v) {
    return __uint_as_float((unsigned)v) + __uint_as_float((unsigned)(v >> 32));
}

// ---------------------------------------------------------------------------
// Kernel 1: global average pool (round-1 proven shape, ~6.8 TB/s).
// One warp per (b,c) row: 196 contiguous floats = 49 float4.
// ---------------------------------------------------------------------------
__global__ __launch_bounds__(256) void pool_kernel(const float* __restrict__ x) {
    int row = (blockIdx.x * 256 + threadIdx.x) >> 5;
    int lane = threadIdx.x & 31;

    const float4* row4 = reinterpret_cast<const float4*>(x + (size_t)row * NHW);
    float4 a = row4[lane];
    float s = (a.x + a.y) + (a.z + a.w);
    if (lane < 17) {
        float4 b4 = row4[32 + lane];
        s += (b4.x + b4.y) + (b4.z + b4.w);
    }
#pragma unroll
    for (int o = 16; o; o >>= 1) s += __shfl_xor_sync(0xffffffffu, s, o);
    if (lane == 0) g_pooled[row] = s * (1.0f / 196.0f);
}

// ---------------------------------------------------------------------------
// Kernel 2: routing. Block = 8 batch rows, 256 threads, grid 512.
// Thread = (expert e in [0,64), k-phase q in [0,4)). acc = 8 rows x 2 matrices
// of f32x2 (32 regs) — low register pressure for 3 blocks/SM.
// Conflict-free LDS.128 (idx = j*4+q), f32x2 FMA.
// ---------------------------------------------------------------------------
__global__ void __launch_bounds__(256, 3) router_kernel(
    const float* __restrict__ noise,
    const float* __restrict__ Wr, const float* __restrict__ br,
    const float* __restrict__ Wn, const float* __restrict__ bn,
    float* __restrict__ out)
{
    __shared__ __align__(16) float sp[ROWS * NC];   // 16 KB pooled tile
    __shared__ __align__(16) float sLog[ROWS][NE];
    __shared__ __align__(16) float sNse[ROWS][NE];

    const int tid  = threadIdx.x;
    const int wid  = tid >> 5;
    const int lane = tid & 31;
    const int b0   = blockIdx.x * ROWS;

    // load pooled tile (float4, coalesced)
    {
        const float4* g4 = reinterpret_cast<const float4*>(g_pooled + (size_t)b0 * NC);
        float4* s4 = reinterpret_cast<float4*>(sp);
#pragma unroll
        for (int i = 0; i < ROWS * NC / 4 / 256; i++)
            s4[tid + i * 256] = g4[tid + i * 256];
    }
    __syncthreads();

    const int q = tid & 3;         // k-phase 0..3
    const int e = tid >> 2;        // expert 0..63

    // acc[r][0] = route, acc[r][1] = noise; each u64 = (even-k, odd-k) partials
    unsigned long long acc[ROWS][2];
#pragma unroll
    for (int r = 0; r < ROWS; r++) { acc[r][0] = 0ull; acc[r][1] = 0ull; }

    const ulonglong2* Wr2 = reinterpret_cast<const ulonglong2*>(Wr) + (size_t)e * (NC / 4);
    const ulonglong2* Wn2 = reinterpret_cast<const ulonglong2*>(Wn) + (size_t)e * (NC / 4);
    const ulonglong2* sp2 = reinterpret_cast<const ulonglong2*>(sp);

#pragma unroll 4
    for (int j = 0; j < NC / 16; j++) {            // 32 iterations
        const int idx = j * 4 + q;                 // float4 index within a row
        ulonglong2 wr = __ldg(&Wr2[idx]);
        ulonglong2 wn = __ldg(&Wn2[idx]);
#pragma unroll
        for (int r = 0; r < ROWS; r++) {
            ulonglong2 p = sp2[r * (NC / 4) + idx];
            FMA2(acc[r][0], p.x, wr.x); FMA2(acc[r][0], p.y, wr.y);
            FMA2(acc[r][1], p.x, wn.x); FMA2(acc[r][1], p.y, wn.y);
        }
    }

    // reduce: pair-sum then butterfly over the 4 phases (lanes tid&3)
    const float brv = br[e], bnv = bn[e];
#pragma unroll
    for (int r = 0; r < ROWS; r++) {
        float vR = pair_sum(acc[r][0]);
        float vN = pair_sum(acc[r][1]);
        vR += __shfl_xor_sync(0xffffffffu, vR, 1);
        vR += __shfl_xor_sync(0xffffffffu, vR, 2);
        vN += __shfl_xor_sync(0xffffffffu, vN, 1);
        vN += __shfl_xor_sync(0xffffffffu, vN, 2);
        if (q == 0) {
            sLog[r][e] = vR + brv;
            sNse[r][e] = vN + bnv;
        }
    }
    __syncthreads();

    // -------- Postprocess: one warp per row; lane owns experts lane, lane+32 --
    float* out_rtr = out;
    float* out_idx = out + (size_t)NB * TOPK;
    float* out_nzy = out + (size_t)2 * NB * TOPK;

    const int r = wid;
    const int b = b0 + r;

    float lg0 = sLog[r][lane], lg1 = sLog[r][lane + 32];
    float nl0 = sNse[r][lane], nl1 = sNse[r][lane + 32];

    float m = fmaxf(lg0, lg1);
#pragma unroll
    for (int o = 16; o; o >>= 1) m = fmaxf(m, __shfl_xor_sync(0xffffffffu, m, o));
    float e0v = __expf(lg0 - m), e1v = __expf(lg1 - m);
    float s = e0v + e1v;
#pragma unroll
    for (int o = 16; o; o >>= 1) s += __shfl_xor_sync(0xffffffffu, s, o);
    float inv = __frcp_rn(s);
    float smL0 = e0v * inv, smL1 = e1v * inv;

    float sp0 = fmaxf(nl0, 0.0f) + log1pf(__expf(-fabsf(nl0)));
    float sp1 = fmaxf(nl1, 0.0f) + log1pf(__expf(-fabsf(nl1)));
    float z0 = noise[(size_t)b * NE + lane]      * sp0;
    float z1 = noise[(size_t)b * NE + lane + 32] * sp1;
    float mn = fmaxf(z0, z1);
#pragma unroll
    for (int o = 16; o; o >>= 1) mn = fmaxf(mn, __shfl_xor_sync(0xffffffffu, mn, o));
    float f0 = __expf(z0 - mn), f1 = __expf(z1 - mn);
    float sn = f0 + f1;
#pragma unroll
    for (int o = 16; o; o >>= 1) sn += __shfl_xor_sync(0xffffffffu, sn, o);
    float invn = __frcp_rn(sn);

    float noisy0 = smL0 + f0 * invn;
    float noisy1 = smL1 + f1 * invn;

    out_nzy[(size_t)b * NE + lane]      = noisy0;
    out_nzy[(size_t)b * NE + lane + 32] = noisy1;

    // top-8: iterative warp argmax; tie-break = lowest index (lax.top_k)
    float v0 = noisy0, v1 = noisy1;
    float topv[TOPK];
    int   topi[TOPK];
#pragma unroll
    for (int k = 0; k < TOPK; k++) {
        float bv; int bi;
        if (v0 >= v1) { bv = v0; bi = lane; }
        else          { bv = v1; bi = lane + 32; }
#pragma unroll
        for (int o = 16; o; o >>= 1) {
            float ov = __shfl_xor_sync(0xffffffffu, bv, o);
            int   oi = __shfl_xor_sync(0xffffffffu, bi, o);
            if (ov > bv || (ov == bv && oi < bi)) { bv = ov; bi = oi; }
        }
        topv[k] = bv; topi[k] = bi;
        if      (bi == lane)      v0 = -INFINITY;
        else if (bi == lane + 32) v1 = -INFINITY;
    }

    float ssum = 0.0f, ev[TOPK];
#pragma unroll
    for (int k = 0; k < TOPK; k++) { ev[k] = __expf(topv[k] - topv[0]); ssum += ev[k]; }
    float invt = __frcp_rn(ssum);

#pragma unroll
    for (int k = 0; k < TOPK; k++) {
        if (lane == k) {
            out_rtr[(size_t)b * TOPK + k] = ev[k] * invt;
            out_idx[(size_t)b * TOPK + k] = (float)topi[k];
        }
    }
}

// ---------------------------------------------------------------------------
extern "C" void kernel_launch(void* const* d_in, const int* in_sizes, int n_in,
                              void* d_out, int out_size) {
    const float* mh      = (const float*)d_in[0];
    const float* noise   = (const float*)d_in[1];
    const float* W_route = (const float*)d_in[2];
    const float* b_route = (const float*)d_in[3];
    const float* W_noise = (const float*)d_in[4];
    const float* b_noise = (const float*)d_in[5];
    float* out = (float*)d_out;

    pool_kernel<<<(NB * NC) / 8, 256>>>(mh);
    router_kernel<<<NB / ROWS, 256>>>(noise, W_route, b_route, W_noise, b_noise, out);
}

// round 11
// speedup vs baseline: 1.1081x; 1.0551x over previous
#include <cuda_runtime.h>
#include <math.h>

#define NB 4096
#define NC 512
#define NHW 196
#define NE 64
#define TOPK 8
#define ROWS 8

// scratch: pooled [B, C] (8 MB) — __device__ global, no allocation
__device__ __align__(16) float g_pooled[NB * NC];

// packed fp32x2 FMA (SASS FFMA2 — only reachable via PTX)
#define FMA2(acc, a, b) \
    asm("fma.rn.f32x2 %0, %1, %2, %0;" : "+l"(acc) : "l"(a), "l"(b))

__device__ __forceinline__ float pair_sum(unsigned long long v) {
    return __uint_as_float((unsigned)v) + __uint_as_float((unsigned)(v >> 32));
}

// ---------------------------------------------------------------------------
// Kernel 1: global average pool (round-1 proven shape) + streaming loads.
// One warp per (b,c) row: 196 contiguous floats = 49 float4. __ldcs marks the
// one-touch stream evict-first so L2 isn't thrashed allocating dead lines.
// ---------------------------------------------------------------------------
__global__ __launch_bounds__(256) void pool_kernel(const float* __restrict__ x) {
    int row = (blockIdx.x * 256 + threadIdx.x) >> 5;
    int lane = threadIdx.x & 31;

    const float4* row4 = reinterpret_cast<const float4*>(x + (size_t)row * NHW);
    float4 a = __ldcs(&row4[lane]);
    float s = (a.x + a.y) + (a.z + a.w);
    if (lane < 17) {
        float4 b4 = __ldcs(&row4[32 + lane]);
        s += (b4.x + b4.y) + (b4.z + b4.w);
    }
#pragma unroll
    for (int o = 16; o; o >>= 1) s += __shfl_xor_sync(0xffffffffu, s, o);
    if (lane == 0) g_pooled[row] = s * (1.0f / 196.0f);
}

// ---------------------------------------------------------------------------
// Kernel 2: routing — byte-identical to the committed round-6 winner.
// Block = 8 batch rows, 256 threads, grid 512. thread = (expert-pair, k-phase),
// f32x2 accumulation, conflict-free LDS.128, E_t=4 (the LDS/regs optimum).
// ---------------------------------------------------------------------------
__global__ __launch_bounds__(256) void router_kernel(
    const float* __restrict__ noise,
    const float* __restrict__ Wr, const float* __restrict__ br,
    const float* __restrict__ Wn, const float* __restrict__ bn,
    float* __restrict__ out)
{
    __shared__ __align__(16) float sp[ROWS * NC];   // 16 KB pooled tile
    __shared__ __align__(16) float sLog[ROWS][NE];
    __shared__ __align__(16) float sNse[ROWS][NE];

    const int tid  = threadIdx.x;
    const int wid  = tid >> 5;
    const int lane = tid & 31;
    const int b0   = blockIdx.x * ROWS;

    {
        const float4* g4 = reinterpret_cast<const float4*>(g_pooled + (size_t)b0 * NC);
        float4* s4 = reinterpret_cast<float4*>(sp);
#pragma unroll
        for (int i = 0; i < ROWS * NC / 4 / 256; i++)
            s4[tid + i * 256] = g4[tid + i * 256];
    }
    __syncthreads();

    const int ph = tid & 7;        // k-phase 0..7
    const int e2 = tid >> 3;       // expert pair 0..31
    const int e0 = e2 * 2, e1 = e0 + 1;

    unsigned long long acc[ROWS][4];
#pragma unroll
    for (int r = 0; r < ROWS; r++)
#pragma unroll
        for (int m = 0; m < 4; m++) acc[r][m] = 0ull;

    const ulonglong2* Wr2 = reinterpret_cast<const ulonglong2*>(Wr);
    const ulonglong2* Wn2 = reinterpret_cast<const ulonglong2*>(Wn);
    const ulonglong2* sp2 = reinterpret_cast<const ulonglong2*>(sp);

#pragma unroll 2
    for (int j = 0; j < NC / 32; j++) {
        const int idx = j * 8 + ph;
        ulonglong2 wr0 = __ldg(&Wr2[e0 * (NC / 4) + idx]);
        ulonglong2 wr1 = __ldg(&Wr2[e1 * (NC / 4) + idx]);
        ulonglong2 wn0 = __ldg(&Wn2[e0 * (NC / 4) + idx]);
        ulonglong2 wn1 = __ldg(&Wn2[e1 * (NC / 4) + idx]);
#pragma unroll
        for (int r = 0; r < ROWS; r++) {
            ulonglong2 p = sp2[r * (NC / 4) + idx];
            FMA2(acc[r][0], p.x, wr0.x); FMA2(acc[r][0], p.y, wr0.y);
            FMA2(acc[r][1], p.x, wr1.x); FMA2(acc[r][1], p.y, wr1.y);
            FMA2(acc[r][2], p.x, wn0.x); FMA2(acc[r][2], p.y, wn0.y);
            FMA2(acc[r][3], p.x, wn1.x); FMA2(acc[r][3], p.y, wn1.y);
        }
    }

    const float br0 = br[e0], br1 = br[e1], bn0 = bn[e0], bn1 = bn[e1];
#pragma unroll
    for (int r = 0; r < ROWS; r++) {
        float vR0 = pair_sum(acc[r][0]);
        float vR1 = pair_sum(acc[r][1]);
        float vN0 = pair_sum(acc[r][2]);
        float vN1 = pair_sum(acc[r][3]);
#pragma unroll
        for (int o = 1; o < 8; o <<= 1) {
            vR0 += __shfl_xor_sync(0xffffffffu, vR0, o);
            vR1 += __shfl_xor_sync(0xffffffffu, vR1, o);
            vN0 += __shfl_xor_sync(0xffffffffu, vN0, o);
            vN1 += __shfl_xor_sync(0xffffffffu, vN1, o);
        }
        if (ph == 0) {
            sLog[r][e0] = vR0 + br0;
            sLog[r][e1] = vR1 + br1;
            sNse[r][e0] = vN0 + bn0;
            sNse[r][e1] = vN1 + bn1;
        }
    }
    __syncthreads();

    // -------- Postprocess: one warp per row; lane owns experts lane, lane+32 --
    float* out_rtr = out;
    float* out_idx = out + (size_t)NB * TOPK;
    float* out_nzy = out + (size_t)2 * NB * TOPK;

    const int r = wid;
    const int b = b0 + r;

    float lg0 = sLog[r][lane], lg1 = sLog[r][lane + 32];
    float nl0 = sNse[r][lane], nl1 = sNse[r][lane + 32];

    float m = fmaxf(lg0, lg1);
#pragma unroll
    for (int o = 16; o; o >>= 1) m = fmaxf(m, __shfl_xor_sync(0xffffffffu, m, o));
    float e0v = __expf(lg0 - m), e1v = __expf(lg1 - m);
    float s = e0v + e1v;
#pragma unroll
    for (int o = 16; o; o >>= 1) s += __shfl_xor_sync(0xffffffffu, s, o);
    float inv = __frcp_rn(s);
    float smL0 = e0v * inv, smL1 = e1v * inv;

    float sp0 = fmaxf(nl0, 0.0f) + log1pf(__expf(-fabsf(nl0)));
    float sp1 = fmaxf(nl1, 0.0f) + log1pf(__expf(-fabsf(nl1)));
    float z0 = noise[(size_t)b * NE + lane]      * sp0;
    float z1 = noise[(size_t)b * NE + lane + 32] * sp1;
    float mn = fmaxf(z0, z1);
#pragma unroll
    for (int o = 16; o; o >>= 1) mn = fmaxf(mn, __shfl_xor_sync(0xffffffffu, mn, o));
    float f0 = __expf(z0 - mn), f1 = __expf(z1 - mn);
    float sn = f0 + f1;
#pragma unroll
    for (int o = 16; o; o >>= 1) sn += __shfl_xor_sync(0xffffffffu, sn, o);
    float invn = __frcp_rn(sn);

    float noisy0 = smL0 + f0 * invn;
    float noisy1 = smL1 + f1 * invn;

    out_nzy[(size_t)b * NE + lane]      = noisy0;
    out_nzy[(size_t)b * NE + lane + 32] = noisy1;

    float v0 = noisy0, v1 = noisy1;
    float topv[TOPK];
    int   topi[TOPK];
#pragma unroll
    for (int k = 0; k < TOPK; k++) {
        float bv; int bi;
        if (v0 >= v1) { bv = v0; bi = lane; }
        else          { bv = v1; bi = lane + 32; }
#pragma unroll
        for (int o = 16; o; o >>= 1) {
            float ov = __shfl_xor_sync(0xffffffffu, bv, o);
            int   oi = __shfl_xor_sync(0xffffffffu, bi, o);
            if (ov > bv || (ov == bv && oi < bi)) { bv = ov; bi = oi; }
        }
        topv[k] = bv; topi[k] = bi;
        if      (bi == lane)      v0 = -INFINITY;
        else if (bi == lane + 32) v1 = -INFINITY;
    }

    float ssum = 0.0f, ev[TOPK];
#pragma unroll
    for (int k = 0; k < TOPK; k++) { ev[k] = __expf(topv[k] - topv[0]); ssum += ev[k]; }
    float invt = __frcp_rn(ssum);

#pragma unroll
    for (int k = 0; k < TOPK; k++) {
        if (lane == k) {
            out_rtr[(size_t)b * TOPK + k] = ev[k] * invt;
            out_idx[(size_t)b * TOPK + k] = (float)topi[k];
        }
    }
}

// ---------------------------------------------------------------------------
extern "C" void kernel_launch(void* const* d_in, const int* in_sizes, int n_in,
                              void* d_out, int out_size) {
    const float* mh      = (const float*)d_in[0];
    const float* noise   = (const float*)d_in[1];
    const float* W_route = (const float*)d_in[2];
    const float* b_route = (const float*)d_in[3];
    const float* W_noise = (const float*)d_in[4];
    const float* b_noise = (const float*)d_in[5];
    float* out = (float*)d_out;

    pool_kernel<<<(NB * NC) / 8, 256>>>(mh);
    router_kernel<<<NB / ROWS, 256>>>(noise, W_route, b_route, W_noise, b_noise, out);
}